// round 8
// baseline (speedup 1.0000x reference)
#include <cuda_runtime.h>
#include <cstdint>

// ---------------------------------------------------------------------------
// Sinkhorn-Knopp, 65536 independent 32x32 fp32 matrices, 10 iterations.
//
// diag-scaling form: iterate only u, v (32-vectors):
//   d_i = sum_j M0[i][j] v_j ;  u_i <- u_i / (u_i d_i + eps)
//   c_j = sum_i M0[i][j] u_i ;  v_j <- v_j / (v_j c_j + eps)
//
// TWO matrices per warp (half-warps), each on a 4x4 lane grid:
//   hl = lane&15, a = hl>>2 (rows 8a..8a+7), b = hl&3 (cols 8b..8b+7).
// Lane owns an 8x8 subtile as 32 f32x2 regs. All shfl_xor masks < 16, so
// every shuffle instruction serves both matrices: 12 SASS SHFL per matrix
// per iteration (R7 needed 20).
//
// xor-slot register layout (all comm is SEL-free shfl_xor):
//   row slot i=2p+e   <-> actual row  8a + 2*(b^p) + e
//   col pair slot k   <-> actual col pair a^k of group b (cols 8b+2(a^k),+1)
//
// Global I/O is perfectly flat (512B per warp instruction over the two
// contiguous matrices). The flat <-> slot transpose goes through per-warp
// smem tiles with row stride 40 floats; chunk order is additionally xored
// by a0 so every LDS.128/STS.128 phase hits 8 distinct bank-quads.
// ---------------------------------------------------------------------------

#define FMA2(d, a, b, c) \
    asm("fma.rn.f32x2 %0, %1, %2, %3;" : "=l"(d) : "l"(a), "l"(b), "l"(c))
#define MUL2(d, a, b) \
    asm("mul.rn.f32x2 %0, %1, %2;" : "=l"(d) : "l"(a), "l"(b))
#define ADD2(d, a, b) \
    asm("add.rn.f32x2 %0, %1, %2;" : "=l"(d) : "l"(a), "l"(b))
#define PACK2(d, lo, hi) \
    asm("mov.b64 %0, {%1, %2};" : "=l"(d) : "f"(lo), "f"(hi))
#define UNPACK2(lo, hi, s) \
    asm("mov.b64 {%0, %1}, %2;" : "=f"(lo), "=f"(hi) : "l"(s))
#define RCPA(d, s) \
    asm("rcp.approx.f32 %0, %1;" : "=f"(d) : "f"(s))
#define EX2A(d, s) \
    asm("ex2.approx.f32 %0, %1;" : "=f"(d) : "f"(s))

using ull = unsigned long long;

static constexpr float    EPS   = 1e-8f;
static constexpr float    SCALE = 14.4269504088896340736f;  // 10 * log2(e)
static constexpr int      WPB   = 4;                        // warps per block
static constexpr int      SROW  = 40;                       // smem row stride
static constexpr unsigned FULL  = 0xFFFFFFFFu;

__device__ __forceinline__ ull shfl_xor64(ull x, int mask) {
    return __shfl_xor_sync(FULL, x, mask);   // 2 SASS SHFLs
}

__global__ __launch_bounds__(WPB * 32, 5)
void sinkhorn_kernel(const float* __restrict__ H,
                     float* __restrict__ Out,
                     int nmat) {
    __shared__ __align__(16) float S[WPB][2][32 * SROW];

    const int lane = threadIdx.x & 31;
    const int wid  = threadIdx.x >> 5;
    const int h    = lane >> 4;          // matrix within warp
    const int hl   = lane & 15;
    const int a    = hl >> 2;            // 0..3 (rows 8a..8a+7)
    const int b    = hl & 3;             // 0..3 (cols 8b..8b+7)
    const int a0   = a & 1;
    const int a1   = a >> 1;

    int m0 = (blockIdx.x * WPB + wid) * 2;
    if (m0 >= nmat) return;              // warp-uniform
    if (m0 + 2 > nmat) m0 = nmat - 2;    // tail: duplicate (identical writes)

    const float4* src = reinterpret_cast<const float4*>(H)  + (size_t)m0 * 256;
    float4*       dst = reinterpret_cast<float4*>(Out)      + (size_t)m0 * 256;

    ull SC2;  PACK2(SC2, SCALE, SCALE);
    ull ONE2; PACK2(ONE2, 1.0f, 1.0f);
    ull EPS2; PACK2(EPS2, EPS, EPS);

    // ---- Flat load of BOTH matrices (512B/inst), exp+clamp, STS.128 ----
#pragma unroll
    for (int k = 0; k < 16; k++) {
        const int f = k * 32 + lane;            // float4 index over 2 matrices
        float4 q = src[f];
        ull p0, p1;
        PACK2(p0, q.x, q.y);
        PACK2(p1, q.z, q.w);
        MUL2(p0, p0, SC2);
        MUL2(p1, p1, SC2);
        float x0, y0, x1, y1;
        UNPACK2(x0, y0, p0); UNPACK2(x1, y1, p1);
        EX2A(x0, x0); EX2A(y0, y0); EX2A(x1, x1); EX2A(y1, y1);
        q.x = fmaxf(x0, EPS); q.y = fmaxf(y0, EPS);
        q.z = fmaxf(x1, EPS); q.w = fmaxf(y1, EPS);
        const int t   = k >> 3;                 // tile (matrix) index
        const int row = (f >> 3) & 31;
        const int ch  = lane & 7;
        *reinterpret_cast<float4*>(&S[wid][t][row * SROW + ch * 4]) = q;
    }
    __syncwarp();

    float* s = S[wid][h];

    // ---- Gather xor-slot registers via conflict-free LDS.128 ----
    // M[2p+e][k] = pair ( m0[8a+2(b^p)+e][8b+2(a^k)], +1 )
    ull M[8][4];
#pragma unroll
    for (int p = 0; p < 4; p++) {
#pragma unroll
        for (int e = 0; e < 2; e++) {
            const int i = 2 * p + e;
            const int R = 8 * a + 2 * (b ^ p) + e;
#pragma unroll
            for (int T = 0; T < 2; T++) {
                const int c  = a0 ^ a1 ^ T;        // chunk (2 col pairs)
                const int kb = 2 * (a0 ^ T);       // slot base for this chunk
                const ulonglong2 q = *reinterpret_cast<const ulonglong2*>(
                    s + R * SROW + 8 * b + 4 * c);
                M[i][kb]     = a0 ? q.y : q.x;
                M[i][kb + 1] = a0 ? q.x : q.y;
            }
        }
    }

    // State: up = u-pair rows (8a+2b, 8a+2b+1); vp = v-pair cols (8b+2a,+1)
    ull up = ONE2, vp = ONE2;
    ull V[4];                       // V[k] = v-pair for pair a^k of group b
    V[0] = ONE2; V[1] = ONE2; V[2] = ONE2; V[3] = ONE2;
    ull U[4];                       // U[p] = u-pair for rows 8a+2(b^p),+1

#pragma unroll 1
    for (int it = 0; it < 10; it++) {
        // ===== Row step =====
        ull D[4];
#pragma unroll
        for (int p = 0; p < 4; p++) {
            float dl[2];
#pragma unroll
            for (int e = 0; e < 2; e++) {
                const int i = 2 * p + e;
                ull acc;
                MUL2(acc, M[i][0], V[0]);
                FMA2(acc, M[i][1], V[1], acc);
                FMA2(acc, M[i][2], V[2], acc);
                FMA2(acc, M[i][3], V[3], acc);
                float x, y; UNPACK2(x, y, acc);
                dl[e] = x + y;
            }
            PACK2(D[p], dl[0], dl[1]);      // partial d-pair, slot p
        }
        {   // reduce over b-quad (masks 2, 1)
            ull t;
            t = shfl_xor64(D[2], 2); ADD2(D[0], D[0], t);
            t = shfl_xor64(D[3], 2); ADD2(D[1], D[1], t);
            t = shfl_xor64(D[1], 1); ADD2(D[0], D[0], t);
        }
        {   // u-pair update
            ull t; FMA2(t, up, D[0], EPS2);
            float tl, th; UNPACK2(tl, th, t);
            float rl, rh; RCPA(rl, tl); RCPA(rh, th);
            ull rp; PACK2(rp, rl, rh);
            MUL2(up, up, rp);
        }
        U[0] = up;
        U[1] = shfl_xor64(up, 1);
        U[2] = shfl_xor64(up, 2);
        U[3] = shfl_xor64(up, 3);

        // ===== Col step =====
        ull C[4];
#pragma unroll
        for (int p = 0; p < 4; p++) {
            float ul, uh; UNPACK2(ul, uh, U[p]);
            ull d0; PACK2(d0, ul, ul);
            ull d1; PACK2(d1, uh, uh);
            const int i0 = 2 * p, i1 = 2 * p + 1;
            if (p == 0) {
#pragma unroll
                for (int k = 0; k < 4; k++) {
                    MUL2(C[k], M[i0][k], d0);
                    FMA2(C[k], M[i1][k], d1, C[k]);
                }
            } else {
#pragma unroll
                for (int k = 0; k < 4; k++) {
                    FMA2(C[k], M[i0][k], d0, C[k]);
                    FMA2(C[k], M[i1][k], d1, C[k]);
                }
            }
        }
        {   // reduce over a-quad (masks 8, 4)
            ull t;
            t = shfl_xor64(C[2], 8); ADD2(C[0], C[0], t);
            t = shfl_xor64(C[3], 8); ADD2(C[1], C[1], t);
            t = shfl_xor64(C[1], 4); ADD2(C[0], C[0], t);
        }
        {   // v-pair update
            ull t; FMA2(t, vp, C[0], EPS2);
            float tl, th; UNPACK2(tl, th, t);
            float rl, rh; RCPA(rl, tl); RCPA(rh, th);
            ull rp; PACK2(rp, rl, rh);
            MUL2(vp, vp, rp);
        }
        V[0] = vp;
        V[1] = shfl_xor64(vp, 4);
        V[2] = shfl_xor64(vp, 8);
        V[3] = shfl_xor64(vp, 12);
    }

    // ---- Epilogue: out[i][j] = u_i * M0[i][j] * v_j ----
#pragma unroll
    for (int p = 0; p < 4; p++) {
        float ul, uh; UNPACK2(ul, uh, U[p]);
#pragma unroll
        for (int e = 0; e < 2; e++) {
            const int i = 2 * p + e;
            const int R = 8 * a + 2 * (b ^ p) + e;
            ull ud; { const float uv = e ? uh : ul; PACK2(ud, uv, uv); }
#pragma unroll
            for (int T = 0; T < 2; T++) {
                const int c  = a0 ^ a1 ^ T;
                const int kb = 2 * (a0 ^ T);
                ull o0, o1;
                MUL2(o0, M[i][kb],     V[kb]);
                MUL2(o0, o0, ud);
                MUL2(o1, M[i][kb + 1], V[kb + 1]);
                MUL2(o1, o1, ud);
                ulonglong2 q;
                q.x = a0 ? o1 : o0;         // undo slot pair-swap
                q.y = a0 ? o0 : o1;
                *reinterpret_cast<ulonglong2*>(
                    s + R * SROW + 8 * b + 4 * c) = q;
            }
        }
    }
    __syncwarp();
#pragma unroll
    for (int k = 0; k < 16; k++) {
        const int f   = k * 32 + lane;
        const int t   = k >> 3;
        const int row = (f >> 3) & 31;
        const int ch  = lane & 7;
        dst[f] = *reinterpret_cast<const float4*>(
            &S[wid][t][row * SROW + ch * 4]);
    }
}

extern "C" void kernel_launch(void* const* d_in, const int* in_sizes, int n_in,
                              void* d_out, int out_size) {
    const float* H   = (const float*)d_in[0];
    float*       out = (float*)d_out;
    const int nmat   = in_sizes[0] / 1024;          // 32*32 per matrix
    const int mpb    = 2 * WPB;                     // matrices per block
    const int blocks = (nmat + mpb - 1) / mpb;
    sinkhorn_kernel<<<blocks, WPB * 32>>>(H, out, nmat);
}

// round 9
// speedup vs baseline: 1.5944x; 1.5944x over previous
#include <cuda_runtime.h>
#include <cstdint>

// ---------------------------------------------------------------------------
// Sinkhorn-Knopp, 65536 independent 32x32 fp32 matrices, 10 iterations.
// R6 structure (best: 123.0us) + register squeeze for occupancy:
// __launch_bounds__(128, 9) forces <=56 regs -> 36 warps/SM (was 64 regs ->
// hard 32-warp RF cap). Core live state is ~48 regs, so the squeeze targets
// prologue/epilogue temps, not the loop.
//
// diag-scaling form: iterate only u, v:
//   d_i = sum_j M0[i][j] v_j ;  u_i <- u_i / (u_i d_i + eps)
//   c_j = sum_i M0[i][j] u_i ;  v_j <- v_j / (v_j c_j + eps)
//
// One warp per matrix, 8x4 lane grid, xor-slot register layout (all comm is
// SEL-free shfl_xor; 20 SASS SHFL/iter). Global I/O perfectly flat; the
// flat <-> slot transpose goes through a per-warp padded smem tile
// (stride 36 floats, all accesses bank-conflict-free).
// ---------------------------------------------------------------------------

#define FMA2(d, a, b, c) \
    asm("fma.rn.f32x2 %0, %1, %2, %3;" : "=l"(d) : "l"(a), "l"(b), "l"(c))
#define MUL2(d, a, b) \
    asm("mul.rn.f32x2 %0, %1, %2;" : "=l"(d) : "l"(a), "l"(b))
#define ADD2(d, a, b) \
    asm("add.rn.f32x2 %0, %1, %2;" : "=l"(d) : "l"(a), "l"(b))
#define PACK2(d, lo, hi) \
    asm("mov.b64 %0, {%1, %2};" : "=l"(d) : "f"(lo), "f"(hi))
#define UNPACK2(lo, hi, s) \
    asm("mov.b64 {%0, %1}, %2;" : "=f"(lo), "=f"(hi) : "l"(s))
#define RCPA(d, s) \
    asm("rcp.approx.f32 %0, %1;" : "=f"(d) : "f"(s))
#define EX2A(d, s) \
    asm("ex2.approx.f32 %0, %1;" : "=f"(d) : "f"(s))

using ull = unsigned long long;

static constexpr float    EPS   = 1e-8f;
static constexpr float    SCALE = 14.4269504088896340736f;  // 10 * log2(e)
static constexpr int      WPB   = 4;                        // warps per block
static constexpr int      SROW  = 36;                       // smem row stride
static constexpr unsigned FULL  = 0xFFFFFFFFu;

__device__ __forceinline__ ull shfl_xor64(ull x, int mask) {
    return __shfl_xor_sync(FULL, x, mask);   // 2 SASS SHFLs
}

__global__ __launch_bounds__(WPB * 32, 9)
void sinkhorn_kernel(const float* __restrict__ H,
                     float* __restrict__ Out,
                     int nmat) {
    __shared__ __align__(16) float S[WPB][32 * SROW];

    const int lane = threadIdx.x & 31;
    const int wid  = threadIdx.x >> 5;
    const int a    = lane >> 2;      // 0..7 (rows 4a..4a+3)
    const int b    = lane & 3;       // 0..3 (cols 8b..8b+7)
    const int g    = a >> 1;         // 0..3 (own col-pair index in group)
    const int al   = a & 1;          // element within own col pair

    const int m = blockIdx.x * WPB + wid;
    if (m >= nmat) return;           // warp-uniform

    float* s = S[wid];
    const float4* src = reinterpret_cast<const float4*>(H)  + (size_t)m * 256;
    float4*       dst = reinterpret_cast<float4*>(Out)      + (size_t)m * 256;

    ull SC2;  PACK2(SC2, SCALE, SCALE);
    ull ONE2; PACK2(ONE2, 1.0f, 1.0f);

    // ---- Flat load (4 lines/inst), scale+exp+clamp, flat STS.128 ----
#pragma unroll
    for (int k = 0; k < 8; k++) {
        const int f = k * 32 + lane;            // float4 index in matrix
        float4 q = src[f];
        ull p0, p1;
        PACK2(p0, q.x, q.y);
        PACK2(p1, q.z, q.w);
        MUL2(p0, p0, SC2);
        MUL2(p1, p1, SC2);
        float x0, y0, x1, y1;
        UNPACK2(x0, y0, p0); UNPACK2(x1, y1, p1);
        EX2A(x0, x0); EX2A(y0, y0); EX2A(x1, x1); EX2A(y1, y1);
        q.x = fmaxf(x0, EPS); q.y = fmaxf(y0, EPS);
        q.z = fmaxf(x1, EPS); q.w = fmaxf(y1, EPS);
        const int row = f >> 3;                 // 8 float4 per row
        const int ch  = f & 7;
        *reinterpret_cast<float4*>(s + row * SROW + ch * 4) = q;
    }
    __syncwarp();

    // ---- Gather xor-slot registers via conflict-free LDS.64 ----
    // M[r][k] = pair ( m0[4a+(b^r)][8b+2(g^k)], +1 )
    ull M[4][4];
#pragma unroll
    for (int r = 0; r < 4; r++) {
        const int R = 4 * a + (b ^ r);
#pragma unroll
        for (int k = 0; k < 4; k++) {
            const int P = 4 * b + (g ^ k);       // global col-pair index
            M[r][k] = *reinterpret_cast<const ull*>(s + R * SROW + 2 * P);
        }
    }

    // State: u = u[4a+b] (scalar), v = v[8b+a] (scalar)
    float u = 1.0f, v = 1.0f;
    ull V[4];                       // V[k] = v-pair for pair g^k of group b
    V[0] = ONE2; V[1] = ONE2; V[2] = ONE2; V[3] = ONE2;
    ull U2[4];                      // U2[r] = (u[4a+(b^r)], same)

#pragma unroll 1
    for (int it = 0; it < 10; it++) {
        // ===== Row step =====
        float D0, D1, D2, D3;
        {
            ull acc;
            MUL2(acc, M[0][0], V[0]); FMA2(acc, M[0][1], V[1], acc);
            FMA2(acc, M[0][2], V[2], acc); FMA2(acc, M[0][3], V[3], acc);
            float x, y; UNPACK2(x, y, acc); D0 = x + y;
            MUL2(acc, M[1][0], V[0]); FMA2(acc, M[1][1], V[1], acc);
            FMA2(acc, M[1][2], V[2], acc); FMA2(acc, M[1][3], V[3], acc);
            UNPACK2(x, y, acc); D1 = x + y;
            MUL2(acc, M[2][0], V[0]); FMA2(acc, M[2][1], V[1], acc);
            FMA2(acc, M[2][2], V[2], acc); FMA2(acc, M[2][3], V[3], acc);
            UNPACK2(x, y, acc); D2 = x + y;
            MUL2(acc, M[3][0], V[0]); FMA2(acc, M[3][1], V[1], acc);
            FMA2(acc, M[3][2], V[2], acc); FMA2(acc, M[3][3], V[3], acc);
            UNPACK2(x, y, acc); D3 = x + y;
        }
        // xor-slot reduce over b-quad (slot r on lane b holds row 4a+(b^r))
        D0 += __shfl_xor_sync(FULL, D2, 2);
        D1 += __shfl_xor_sync(FULL, D3, 2);
        D0 += __shfl_xor_sync(FULL, D1, 1);      // full d[4a+b]
        { float t = fmaf(u, D0, EPS); float r0; RCPA(r0, t); u *= r0; }
        // u allgather into row slots
        {
            float u1 = __shfl_xor_sync(FULL, u, 1);
            float u2 = __shfl_xor_sync(FULL, u, 2);
            float u3 = __shfl_xor_sync(FULL, u, 3);
            PACK2(U2[0], u,  u ); PACK2(U2[1], u1, u1);
            PACK2(U2[2], u2, u2); PACK2(U2[3], u3, u3);
        }

        // ===== Col step =====
        ull C0, C1, C2, C3;
        MUL2(C0, M[0][0], U2[0]); FMA2(C0, M[1][0], U2[1], C0);
        FMA2(C0, M[2][0], U2[2], C0); FMA2(C0, M[3][0], U2[3], C0);
        MUL2(C1, M[0][1], U2[0]); FMA2(C1, M[1][1], U2[1], C1);
        FMA2(C1, M[2][1], U2[2], C1); FMA2(C1, M[3][1], U2[3], C1);
        MUL2(C2, M[0][2], U2[0]); FMA2(C2, M[1][2], U2[1], C2);
        FMA2(C2, M[2][2], U2[2], C2); FMA2(C2, M[3][2], U2[3], C2);
        MUL2(C3, M[0][3], U2[0]); FMA2(C3, M[1][3], U2[1], C3);
        FMA2(C3, M[2][3], U2[2], C3); FMA2(C3, M[3][3], U2[3], C3);
        // xor-slot reduce over the 8 a-lanes
        {
            ull t;
            t = shfl_xor64(C2, 16); ADD2(C0, C0, t);
            t = shfl_xor64(C3, 16); ADD2(C1, C1, t);
            t = shfl_xor64(C1, 8);  ADD2(C0, C0, t);
        }
        // final mask-4 stage as a single scalar exchange:
        float cx, cy; UNPACK2(cx, cy, C0);
        const float send = al ? cx : cy;         // element partner needs
        const float recv = __shfl_xor_sync(FULL, send, 4);
        const float mine = al ? cy : cx;
        const float cs   = mine + recv;          // c[8b+2g+al] = c[8b+a]
        { float t = fmaf(v, cs, EPS); float r0; RCPA(r0, t); v *= r0; }
        // v allgather into col-pair slots
        {
            float t4 = __shfl_xor_sync(FULL, v, 4);    // pair partner
            const float lo = al ? t4 : v;
            const float hi = al ? v  : t4;
            PACK2(V[0], lo, hi);                       // own pair g
            V[1] = shfl_xor64(V[0], 8);
            V[2] = shfl_xor64(V[0], 16);
            V[3] = shfl_xor64(V[0], 24);
        }
    }

    // ---- Epilogue: out[i][j] = u_i * M0[i][j] * v_j ----
    // STS.64 per slot (conflict-free), then flat LDS.128 + flat STG.128.
#pragma unroll
    for (int r = 0; r < 4; r++) {
        const int R = 4 * a + (b ^ r);
#pragma unroll
        for (int k = 0; k < 4; k++) {
            const int P = 4 * b + (g ^ k);
            ull o;
            MUL2(o, M[r][k], V[k]);
            MUL2(o, o, U2[r]);
            *reinterpret_cast<ull*>(s + R * SROW + 2 * P) = o;
        }
    }
    __syncwarp();
#pragma unroll
    for (int k = 0; k < 8; k++) {
        const int f   = k * 32 + lane;
        const int row = f >> 3;
        const int ch  = f & 7;
        dst[f] = *reinterpret_cast<const float4*>(s + row * SROW + ch * 4);
    }
}

extern "C" void kernel_launch(void* const* d_in, const int* in_sizes, int n_in,
                              void* d_out, int out_size) {
    const float* H   = (const float*)d_in[0];
    float*       out = (float*)d_out;
    const int nmat   = in_sizes[0] / 1024;          // 32*32 per matrix
    const int blocks = (nmat + WPB - 1) / WPB;
    sinkhorn_kernel<<<blocks, WPB * 32>>>(H, out, nmat);
}

// round 10
// speedup vs baseline: 1.7122x; 1.0739x over previous
#include <cuda_runtime.h>
#include <cstdint>

// ---------------------------------------------------------------------------
// Sinkhorn-Knopp, 65536 independent 32x32 fp32 matrices, 10 iterations.
// R6 champion structure + algebraic update simplification:
//   row normalize:  u' = u/(u*d + eps)  ~=  1/d     (eps=1e-8, sums Theta(1))
//   col normalize:  v' = v/(v*c + eps)  ~=  1/c
// Each update becomes a single RCP; u/v are no longer carried state.
// Added rel-err ~2e-7, far under the 1e-3 gate.
//
// One warp per matrix, 8x4 lane grid, xor-slot register layout (all comm is
// SEL-free shfl_xor; 20 SASS SHFL/iter = comm floor for this partition).
// Global I/O perfectly flat (512B/warp-inst); flat <-> slot transpose goes
// through a per-warp padded smem tile (stride 36 floats, conflict-free).
// ---------------------------------------------------------------------------

#define FMA2(d, a, b, c) \
    asm("fma.rn.f32x2 %0, %1, %2, %3;" : "=l"(d) : "l"(a), "l"(b), "l"(c))
#define MUL2(d, a, b) \
    asm("mul.rn.f32x2 %0, %1, %2;" : "=l"(d) : "l"(a), "l"(b))
#define ADD2(d, a, b) \
    asm("add.rn.f32x2 %0, %1, %2;" : "=l"(d) : "l"(a), "l"(b))
#define PACK2(d, lo, hi) \
    asm("mov.b64 %0, {%1, %2};" : "=l"(d) : "f"(lo), "f"(hi))
#define UNPACK2(lo, hi, s) \
    asm("mov.b64 {%0, %1}, %2;" : "=f"(lo), "=f"(hi) : "l"(s))
#define RCPA(d, s) \
    asm("rcp.approx.f32 %0, %1;" : "=f"(d) : "f"(s))
#define EX2A(d, s) \
    asm("ex2.approx.f32 %0, %1;" : "=f"(d) : "f"(s))

using ull = unsigned long long;

static constexpr float    EPS   = 1e-8f;
static constexpr float    SCALE = 14.4269504088896340736f;  // 10 * log2(e)
static constexpr int      WPB   = 4;                        // warps per block
static constexpr int      SROW  = 36;                       // smem row stride
static constexpr unsigned FULL  = 0xFFFFFFFFu;

__device__ __forceinline__ ull shfl_xor64(ull x, int mask) {
    return __shfl_xor_sync(FULL, x, mask);   // 2 SASS SHFLs
}

__global__ __launch_bounds__(WPB * 32, 8)
void sinkhorn_kernel(const float* __restrict__ H,
                     float* __restrict__ Out,
                     int nmat) {
    __shared__ __align__(16) float S[WPB][32 * SROW];

    const int lane = threadIdx.x & 31;
    const int wid  = threadIdx.x >> 5;
    const int a    = lane >> 2;      // 0..7 (rows 4a..4a+3)
    const int b    = lane & 3;       // 0..3 (cols 8b..8b+7)
    const int g    = a >> 1;         // 0..3 (own col-pair index in group)
    const int al   = a & 1;          // element within own col pair

    const int m = blockIdx.x * WPB + wid;
    if (m >= nmat) return;           // warp-uniform

    float* s = S[wid];
    const float4* src = reinterpret_cast<const float4*>(H)  + (size_t)m * 256;
    float4*       dst = reinterpret_cast<float4*>(Out)      + (size_t)m * 256;

    ull SC2;  PACK2(SC2, SCALE, SCALE);
    ull ONE2; PACK2(ONE2, 1.0f, 1.0f);

    // ---- Flat load (4 lines/inst), scale+exp+clamp, flat STS.128 ----
#pragma unroll
    for (int k = 0; k < 8; k++) {
        const int f = k * 32 + lane;            // float4 index in matrix
        float4 q = src[f];
        ull p0, p1;
        PACK2(p0, q.x, q.y);
        PACK2(p1, q.z, q.w);
        MUL2(p0, p0, SC2);
        MUL2(p1, p1, SC2);
        float x0, y0, x1, y1;
        UNPACK2(x0, y0, p0); UNPACK2(x1, y1, p1);
        EX2A(x0, x0); EX2A(y0, y0); EX2A(x1, x1); EX2A(y1, y1);
        q.x = fmaxf(x0, EPS); q.y = fmaxf(y0, EPS);
        q.z = fmaxf(x1, EPS); q.w = fmaxf(y1, EPS);
        const int row = f >> 3;                 // 8 float4 per row
        const int ch  = f & 7;
        *reinterpret_cast<float4*>(s + row * SROW + ch * 4) = q;
    }
    __syncwarp();

    // ---- Gather xor-slot registers via conflict-free LDS.64 ----
    // M[r][k] = pair ( m0[4a+(b^r)][8b+2(g^k)], +1 )
    ull M[4][4];
#pragma unroll
    for (int r = 0; r < 4; r++) {
        const int R = 4 * a + (b ^ r);
#pragma unroll
        for (int k = 0; k < 4; k++) {
            const int P = 4 * b + (g ^ k);       // global col-pair index
            M[r][k] = *reinterpret_cast<const ull*>(s + R * SROW + 2 * P);
        }
    }

    ull V[4];                       // V[k] = v-pair for pair g^k of group b
    V[0] = ONE2; V[1] = ONE2; V[2] = ONE2; V[3] = ONE2;
    ull U2[4];                      // U2[r] = (u[4a+(b^r)], same)

#pragma unroll 1
    for (int it = 0; it < 10; it++) {
        // ===== Row step: d = M0 v ; u = 1/d =====
        float D0, D1, D2, D3;
        {
            ull acc;
            MUL2(acc, M[0][0], V[0]); FMA2(acc, M[0][1], V[1], acc);
            FMA2(acc, M[0][2], V[2], acc); FMA2(acc, M[0][3], V[3], acc);
            float x, y; UNPACK2(x, y, acc); D0 = x + y;
            MUL2(acc, M[1][0], V[0]); FMA2(acc, M[1][1], V[1], acc);
            FMA2(acc, M[1][2], V[2], acc); FMA2(acc, M[1][3], V[3], acc);
            UNPACK2(x, y, acc); D1 = x + y;
            MUL2(acc, M[2][0], V[0]); FMA2(acc, M[2][1], V[1], acc);
            FMA2(acc, M[2][2], V[2], acc); FMA2(acc, M[2][3], V[3], acc);
            UNPACK2(x, y, acc); D2 = x + y;
            MUL2(acc, M[3][0], V[0]); FMA2(acc, M[3][1], V[1], acc);
            FMA2(acc, M[3][2], V[2], acc); FMA2(acc, M[3][3], V[3], acc);
            UNPACK2(x, y, acc); D3 = x + y;
        }
        // xor-slot reduce over b-quad (slot r on lane b holds row 4a+(b^r))
        D0 += __shfl_xor_sync(FULL, D2, 2);
        D1 += __shfl_xor_sync(FULL, D3, 2);
        D0 += __shfl_xor_sync(FULL, D1, 1);      // full d[4a+b]
        float u; RCPA(u, D0);                    // u = 1/d (eps dropped)
        // u allgather into row slots
        {
            float u1 = __shfl_xor_sync(FULL, u, 1);
            float u2 = __shfl_xor_sync(FULL, u, 2);
            float u3 = __shfl_xor_sync(FULL, u, 3);
            PACK2(U2[0], u,  u ); PACK2(U2[1], u1, u1);
            PACK2(U2[2], u2, u2); PACK2(U2[3], u3, u3);
        }

        // ===== Col step: c = M0^T u ; v = 1/c =====
        ull C0, C1, C2, C3;
        MUL2(C0, M[0][0], U2[0]); FMA2(C0, M[1][0], U2[1], C0);
        FMA2(C0, M[2][0], U2[2], C0); FMA2(C0, M[3][0], U2[3], C0);
        MUL2(C1, M[0][1], U2[0]); FMA2(C1, M[1][1], U2[1], C1);
        FMA2(C1, M[2][1], U2[2], C1); FMA2(C1, M[3][1], U2[3], C1);
        MUL2(C2, M[0][2], U2[0]); FMA2(C2, M[1][2], U2[1], C2);
        FMA2(C2, M[2][2], U2[2], C2); FMA2(C2, M[3][2], U2[3], C2);
        MUL2(C3, M[0][3], U2[0]); FMA2(C3, M[1][3], U2[1], C3);
        FMA2(C3, M[2][3], U2[2], C3); FMA2(C3, M[3][3], U2[3], C3);
        // xor-slot reduce over the 8 a-lanes
        {
            ull t;
            t = shfl_xor64(C2, 16); ADD2(C0, C0, t);
            t = shfl_xor64(C3, 16); ADD2(C1, C1, t);
            t = shfl_xor64(C1, 8);  ADD2(C0, C0, t);
        }
        // final mask-4 stage as a single scalar exchange:
        float cx, cy; UNPACK2(cx, cy, C0);
        const float send = al ? cx : cy;         // element partner needs
        const float recv = __shfl_xor_sync(FULL, send, 4);
        const float mine = al ? cy : cx;
        const float cs   = mine + recv;          // c[8b+2g+al] = c[8b+a]
        float v; RCPA(v, cs);                    // v = 1/c (eps dropped)
        // v allgather into col-pair slots
        {
            float t4 = __shfl_xor_sync(FULL, v, 4);    // pair partner
            const float lo = al ? t4 : v;
            const float hi = al ? v  : t4;
            PACK2(V[0], lo, hi);                       // own pair g
            V[1] = shfl_xor64(V[0], 8);
            V[2] = shfl_xor64(V[0], 16);
            V[3] = shfl_xor64(V[0], 24);
        }
    }

    // ---- Epilogue: out[i][j] = u_i * M0[i][j] * v_j ----
    // STS.64 per slot (conflict-free), then flat LDS.128 + flat STG.128.
#pragma unroll
    for (int r = 0; r < 4; r++) {
        const int R = 4 * a + (b ^ r);
#pragma unroll
        for (int k = 0; k < 4; k++) {
            const int P = 4 * b + (g ^ k);
            ull o;
            MUL2(o, M[r][k], V[k]);
            MUL2(o, o, U2[r]);
            *reinterpret_cast<ull*>(s + R * SROW + 2 * P) = o;
        }
    }
    __syncwarp();
#pragma unroll
    for (int k = 0; k < 8; k++) {
        const int f   = k * 32 + lane;
        const int row = f >> 3;
        const int ch  = f & 7;
        dst[f] = *reinterpret_cast<const float4*>(s + row * SROW + ch * 4);
    }
}

extern "C" void kernel_launch(void* const* d_in, const int* in_sizes, int n_in,
                              void* d_out, int out_size) {
    const float* H   = (const float*)d_in[0];
    float*       out = (float*)d_out;
    const int nmat   = in_sizes[0] / 1024;          // 32*32 per matrix
    const int blocks = (nmat + WPB - 1) / WPB;
    sinkhorn_kernel<<<blocks, WPB * 32>>>(H, out, nmat);
}

// round 11
// speedup vs baseline: 1.7384x; 1.0153x over previous
#include <cuda_runtime.h>
#include <cstdint>

// ---------------------------------------------------------------------------
// Sinkhorn-Knopp, 65536 independent 32x32 fp32 matrices, 10 iterations.
//
// diag-scaling: iterate only u, v; updates simplified (eps negligible since
// sums are Theta(1)):  u = 1/d ,  v = 1/c  -- single RCP each.
//
// One warp per matrix, 8x4 lane grid: a = lane>>2 (rows 4a..4a+3),
// b = lane&3 (cols 8b..8b+7), g = a>>1. xor-slot REGISTER layout:
//   row slot r      <-> actual row       4a + (b^r)
//   col pair slot k <-> actual col pair  g^k of group b (cols 8b+2(g^k),+1)
// All cross-lane comm is SEL-free shfl_xor (20 SASS SHFL/iter = floor).
//
// Global I/O perfectly flat (512B/warp-inst). The flat <-> slot transpose
// goes through a per-warp padded smem tile (stride 36 floats); ALL bridge
// ops are 128-bit and bank-conflict-free (quad bank (9R+Q)&7 is a
// permutation within every quarter-warp phase). Column xor realized by a
// one-time g0 pair swap in registers.
// ---------------------------------------------------------------------------

#define FMA2(d, a, b, c) \
    asm("fma.rn.f32x2 %0, %1, %2, %3;" : "=l"(d) : "l"(a), "l"(b), "l"(c))
#define MUL2(d, a, b) \
    asm("mul.rn.f32x2 %0, %1, %2;" : "=l"(d) : "l"(a), "l"(b))
#define ADD2(d, a, b) \
    asm("add.rn.f32x2 %0, %1, %2;" : "=l"(d) : "l"(a), "l"(b))
#define PACK2(d, lo, hi) \
    asm("mov.b64 %0, {%1, %2};" : "=l"(d) : "f"(lo), "f"(hi))
#define UNPACK2(lo, hi, s) \
    asm("mov.b64 {%0, %1}, %2;" : "=f"(lo), "=f"(hi) : "l"(s))
#define RCPA(d, s) \
    asm("rcp.approx.f32 %0, %1;" : "=f"(d) : "f"(s))
#define EX2A(d, s) \
    asm("ex2.approx.f32 %0, %1;" : "=f"(d) : "f"(s))

using ull = unsigned long long;

static constexpr float    EPS   = 1e-8f;
static constexpr float    SCALE = 14.4269504088896340736f;  // 10 * log2(e)
static constexpr int      WPB   = 4;                        // warps per block
static constexpr int      SROW  = 36;                       // smem row stride
static constexpr unsigned FULL  = 0xFFFFFFFFu;

__device__ __forceinline__ ull shfl_xor64(ull x, int mask) {
    return __shfl_xor_sync(FULL, x, mask);   // 2 SASS SHFLs
}

__global__ __launch_bounds__(WPB * 32, 8)
void sinkhorn_kernel(const float* __restrict__ H,
                     float* __restrict__ Out,
                     int nmat) {
    __shared__ __align__(16) float S[WPB][32 * SROW];

    const int lane = threadIdx.x & 31;
    const int wid  = threadIdx.x >> 5;
    const int a    = lane >> 2;      // 0..7 (rows 4a..4a+3)
    const int b    = lane & 3;       // 0..3 (cols 8b..8b+7)
    const int g    = a >> 1;         // 0..3 (own col-pair index in group)
    const int al   = a & 1;          // element within own col pair
    const int g0   = g & 1;          // pair-swap bit
    const int g1   = g >> 1;         // chunk-select bit

    const int m = blockIdx.x * WPB + wid;
    if (m >= nmat) return;           // warp-uniform

    float* s = S[wid];
    const float4* src = reinterpret_cast<const float4*>(H)  + (size_t)m * 256;
    float4*       dst = reinterpret_cast<float4*>(Out)      + (size_t)m * 256;

    ull SC2;  PACK2(SC2, SCALE, SCALE);
    ull ONE2; PACK2(ONE2, 1.0f, 1.0f);

    // ---- Flat load (4 lines/inst), scale+exp+clamp, flat STS.128 ----
#pragma unroll
    for (int k = 0; k < 8; k++) {
        const int f = k * 32 + lane;            // float4 index in matrix
        float4 q = src[f];
        ull p0, p1;
        PACK2(p0, q.x, q.y);
        PACK2(p1, q.z, q.w);
        MUL2(p0, p0, SC2);
        MUL2(p1, p1, SC2);
        float x0, y0, x1, y1;
        UNPACK2(x0, y0, p0); UNPACK2(x1, y1, p1);
        EX2A(x0, x0); EX2A(y0, y0); EX2A(x1, x1); EX2A(y1, y1);
        q.x = fmaxf(x0, EPS); q.y = fmaxf(y0, EPS);
        q.z = fmaxf(x1, EPS); q.w = fmaxf(y1, EPS);
        const int row = f >> 3;                 // 8 float4 per row
        const int ch  = f & 7;
        *reinterpret_cast<float4*>(s + row * SROW + ch * 4) = q;
    }
    __syncwarp();

    // ---- Gather xor-slot registers via conflict-free LDS.128 ----
    // chunk Q = 2b + (g1^T) holds col pairs 2Q (lo) and 2Q+1 (hi);
    // slot 2T is the one whose pair-bit0 == g0.
    ull M[4][4];
#pragma unroll
    for (int r = 0; r < 4; r++) {
        const int R = 4 * a + (b ^ r);
#pragma unroll
        for (int T = 0; T < 2; T++) {
            const int Q = 2 * b + (g1 ^ T);
            const ulonglong2 q =
                *reinterpret_cast<const ulonglong2*>(s + R * SROW + 4 * Q);
            M[r][2 * T]     = g0 ? q.y : q.x;
            M[r][2 * T + 1] = g0 ? q.x : q.y;
        }
    }

    ull V[4];                       // V[k] = v-pair for pair g^k of group b
    V[0] = ONE2; V[1] = ONE2; V[2] = ONE2; V[3] = ONE2;
    ull U2[4];                      // U2[r] = (u[4a+(b^r)], same)

#pragma unroll 1
    for (int it = 0; it < 10; it++) {
        // ===== Row step: d = M0 v ; u = 1/d =====
        float D0, D1, D2, D3;
        {
            ull acc;
            MUL2(acc, M[0][0], V[0]); FMA2(acc, M[0][1], V[1], acc);
            FMA2(acc, M[0][2], V[2], acc); FMA2(acc, M[0][3], V[3], acc);
            float x, y; UNPACK2(x, y, acc); D0 = x + y;
            MUL2(acc, M[1][0], V[0]); FMA2(acc, M[1][1], V[1], acc);
            FMA2(acc, M[1][2], V[2], acc); FMA2(acc, M[1][3], V[3], acc);
            UNPACK2(x, y, acc); D1 = x + y;
            MUL2(acc, M[2][0], V[0]); FMA2(acc, M[2][1], V[1], acc);
            FMA2(acc, M[2][2], V[2], acc); FMA2(acc, M[2][3], V[3], acc);
            UNPACK2(x, y, acc); D2 = x + y;
            MUL2(acc, M[3][0], V[0]); FMA2(acc, M[3][1], V[1], acc);
            FMA2(acc, M[3][2], V[2], acc); FMA2(acc, M[3][3], V[3], acc);
            UNPACK2(x, y, acc); D3 = x + y;
        }
        // xor-slot reduce over b-quad (slot r on lane b holds row 4a+(b^r))
        D0 += __shfl_xor_sync(FULL, D2, 2);
        D1 += __shfl_xor_sync(FULL, D3, 2);
        D0 += __shfl_xor_sync(FULL, D1, 1);      // full d[4a+b]
        float u; RCPA(u, D0);                    // u = 1/d
        // u allgather into row slots
        {
            float u1 = __shfl_xor_sync(FULL, u, 1);
            float u2 = __shfl_xor_sync(FULL, u, 2);
            float u3 = __shfl_xor_sync(FULL, u, 3);
            PACK2(U2[0], u,  u ); PACK2(U2[1], u1, u1);
            PACK2(U2[2], u2, u2); PACK2(U2[3], u3, u3);
        }

        // ===== Col step: c = M0^T u ; v = 1/c  (dual accumulators) =====
        ull C0, C1, C2, C3, B0, B1, B2, B3;
        MUL2(C0, M[0][0], U2[0]); FMA2(C0, M[1][0], U2[1], C0);
        MUL2(B0, M[2][0], U2[2]); FMA2(B0, M[3][0], U2[3], B0);
        MUL2(C1, M[0][1], U2[0]); FMA2(C1, M[1][1], U2[1], C1);
        MUL2(B1, M[2][1], U2[2]); FMA2(B1, M[3][1], U2[3], B1);
        MUL2(C2, M[0][2], U2[0]); FMA2(C2, M[1][2], U2[1], C2);
        MUL2(B2, M[2][2], U2[2]); FMA2(B2, M[3][2], U2[3], B2);
        MUL2(C3, M[0][3], U2[0]); FMA2(C3, M[1][3], U2[1], C3);
        MUL2(B3, M[2][3], U2[2]); FMA2(B3, M[3][3], U2[3], B3);
        ADD2(C0, C0, B0); ADD2(C1, C1, B1);
        ADD2(C2, C2, B2); ADD2(C3, C3, B3);
        // xor-slot reduce over the 8 a-lanes
        {
            ull t;
            t = shfl_xor64(C2, 16); ADD2(C0, C0, t);
            t = shfl_xor64(C3, 16); ADD2(C1, C1, t);
            t = shfl_xor64(C1, 8);  ADD2(C0, C0, t);
        }
        // final mask-4 stage as a single scalar exchange:
        float cx, cy; UNPACK2(cx, cy, C0);
        const float send = al ? cx : cy;         // element partner needs
        const float recv = __shfl_xor_sync(FULL, send, 4);
        const float mine = al ? cy : cx;
        const float cs   = mine + recv;          // c[8b+2g+al] = c[8b+a]
        float v; RCPA(v, cs);                    // v = 1/c
        // v allgather into col-pair slots
        {
            float t4 = __shfl_xor_sync(FULL, v, 4);    // pair partner
            const float lo = al ? t4 : v;
            const float hi = al ? v  : t4;
            PACK2(V[0], lo, hi);                       // own pair g
            V[1] = shfl_xor64(V[0], 8);
            V[2] = shfl_xor64(V[0], 16);
            V[3] = shfl_xor64(V[0], 24);
        }
    }

    // ---- Epilogue: out[i][j] = u_i * M0[i][j] * v_j ----
    // STS.128 per chunk (conflict-free), then flat LDS.128 + flat STG.128.
#pragma unroll
    for (int r = 0; r < 4; r++) {
        const int R = 4 * a + (b ^ r);
#pragma unroll
        for (int T = 0; T < 2; T++) {
            const int Q = 2 * b + (g1 ^ T);
            ull o0, o1;
            MUL2(o0, M[r][2 * T],     V[2 * T]);
            MUL2(o0, o0, U2[r]);
            MUL2(o1, M[r][2 * T + 1], V[2 * T + 1]);
            MUL2(o1, o1, U2[r]);
            ulonglong2 q;
            q.x = g0 ? o1 : o0;      // undo slot pair-swap
            q.y = g0 ? o0 : o1;
            *reinterpret_cast<ulonglong2*>(s + R * SROW + 4 * Q) = q;
        }
    }
    __syncwarp();
#pragma unroll
    for (int k = 0; k < 8; k++) {
        const int f   = k * 32 + lane;
        const int row = f >> 3;
        const int ch  = f & 7;
        dst[f] = *reinterpret_cast<const float4*>(s + row * SROW + ch * 4);
    }
}

extern "C" void kernel_launch(void* const* d_in, const int* in_sizes, int n_in,
                              void* d_out, int out_size) {
    const float* H   = (const float*)d_in[0];
    float*       out = (float*)d_out;
    const int nmat   = in_sizes[0] / 1024;          // 32*32 per matrix
    const int blocks = (nmat + WPB - 1) / WPB;
    sinkhorn_kernel<<<blocks, WPB * 32>>>(H, out, nmat);
}

// round 12
// speedup vs baseline: 1.8675x; 1.0742x over previous
#include <cuda_runtime.h>
#include <cstdint>

// ---------------------------------------------------------------------------
// Sinkhorn-Knopp, 65536 independent 32x32 fp32 matrices, 10 iterations.
//
// diag-scaling: iterate only u, v; updates simplified (eps negligible since
// sums are Theta(1)):  u = 1/d ,  v = 1/c  -- single RCP each.
//
// One warp per matrix, 8x4 lane grid: a = lane>>2 (rows 4a..4a+3),
// b = lane&3 (cols 8b..8b+7), g = a>>1. xor-slot REGISTER layout:
//   row slot r      <-> actual row       4a + (b^r)
//   col pair slot k <-> actual col pair  g^k of group b (cols 8b+2(g^k),+1)
// All cross-lane comm is SEL-free shfl_xor (20 SASS SHFL/iter = floor).
//
// Global I/O perfectly flat. Input bridges flat->slot through a per-warp
// padded smem tile (stride 36, conflict-free 128-bit ops). EPILOGUE does NOT
// bridge the result tile: the smem tile still holds flat exp(M0), so we STS
// only the final u,v vectors (2 wf) and compute out = u_i * M0 * v_j from
// flat reads (broadcast LDS for u, one LDS.128 for the v chunk). This cuts
// ~27 L1 wavefronts/matrix off the binding resource and also lets the last
// iteration skip its v-allgather entirely.
// ---------------------------------------------------------------------------

#define FMA2(d, a, b, c) \
    asm("fma.rn.f32x2 %0, %1, %2, %3;" : "=l"(d) : "l"(a), "l"(b), "l"(c))
#define MUL2(d, a, b) \
    asm("mul.rn.f32x2 %0, %1, %2;" : "=l"(d) : "l"(a), "l"(b))
#define ADD2(d, a, b) \
    asm("add.rn.f32x2 %0, %1, %2;" : "=l"(d) : "l"(a), "l"(b))
#define PACK2(d, lo, hi) \
    asm("mov.b64 %0, {%1, %2};" : "=l"(d) : "f"(lo), "f"(hi))
#define UNPACK2(lo, hi, s) \
    asm("mov.b64 {%0, %1}, %2;" : "=f"(lo), "=f"(hi) : "l"(s))
#define RCPA(d, s) \
    asm("rcp.approx.f32 %0, %1;" : "=f"(d) : "f"(s))
#define EX2A(d, s) \
    asm("ex2.approx.f32 %0, %1;" : "=f"(d) : "f"(s))

using ull = unsigned long long;

static constexpr float    EPS   = 1e-8f;
static constexpr float    SCALE = 14.4269504088896340736f;  // 10 * log2(e)
static constexpr int      WPB   = 4;                        // warps per block
static constexpr int      SROW  = 36;                       // smem row stride
static constexpr unsigned FULL  = 0xFFFFFFFFu;

__device__ __forceinline__ ull shfl_xor64(ull x, int mask) {
    return __shfl_xor_sync(FULL, x, mask);   // 2 SASS SHFLs
}

__global__ __launch_bounds__(WPB * 32, 8)
void sinkhorn_kernel(const float* __restrict__ H,
                     float* __restrict__ Out,
                     int nmat) {
    // per-warp: 32x32 padded tile + u[32] + v[32]
    __shared__ __align__(16) float S[WPB][32 * SROW + 64];

    const int lane = threadIdx.x & 31;
    const int wid  = threadIdx.x >> 5;
    const int a    = lane >> 2;      // 0..7 (rows 4a..4a+3)
    const int b    = lane & 3;       // 0..3 (cols 8b..8b+7)
    const int g    = a >> 1;         // 0..3 (own col-pair index in group)
    const int al   = a & 1;          // element within own col pair
    const int g0   = g & 1;          // pair-swap bit
    const int g1   = g >> 1;         // chunk-select bit

    const int m = blockIdx.x * WPB + wid;
    if (m >= nmat) return;           // warp-uniform

    float* s  = S[wid];
    float* su = S[wid] + 32 * SROW;        // u[32]
    float* sv = S[wid] + 32 * SROW + 32;   // v[32]
    const float4* src = reinterpret_cast<const float4*>(H)  + (size_t)m * 256;
    float4*       dst = reinterpret_cast<float4*>(Out)      + (size_t)m * 256;

    ull SC2;  PACK2(SC2, SCALE, SCALE);
    ull ONE2; PACK2(ONE2, 1.0f, 1.0f);

    // ---- Flat load (4 lines/inst), scale+exp+clamp, flat STS.128 ----
#pragma unroll
    for (int k = 0; k < 8; k++) {
        const int f = k * 32 + lane;            // float4 index in matrix
        float4 q = src[f];
        ull p0, p1;
        PACK2(p0, q.x, q.y);
        PACK2(p1, q.z, q.w);
        MUL2(p0, p0, SC2);
        MUL2(p1, p1, SC2);
        float x0, y0, x1, y1;
        UNPACK2(x0, y0, p0); UNPACK2(x1, y1, p1);
        EX2A(x0, x0); EX2A(y0, y0); EX2A(x1, x1); EX2A(y1, y1);
        q.x = fmaxf(x0, EPS); q.y = fmaxf(y0, EPS);
        q.z = fmaxf(x1, EPS); q.w = fmaxf(y1, EPS);
        const int row = f >> 3;                 // 8 float4 per row
        const int ch  = f & 7;
        *reinterpret_cast<float4*>(s + row * SROW + ch * 4) = q;
    }
    __syncwarp();

    // ---- Gather xor-slot registers via conflict-free LDS.128 ----
    // chunk Q = 2b + (g1^T) holds col pairs 2Q (lo) and 2Q+1 (hi);
    // slot 2T is the one whose pair-bit0 == g0.
    ull M[4][4];
#pragma unroll
    for (int r = 0; r < 4; r++) {
        const int R = 4 * a + (b ^ r);
#pragma unroll
        for (int T = 0; T < 2; T++) {
            const int Q = 2 * b + (g1 ^ T);
            const ulonglong2 q =
                *reinterpret_cast<const ulonglong2*>(s + R * SROW + 4 * Q);
            M[r][2 * T]     = g0 ? q.y : q.x;
            M[r][2 * T + 1] = g0 ? q.x : q.y;
        }
    }

    ull V[4];                       // V[k] = v-pair for pair g^k of group b
    V[0] = ONE2; V[1] = ONE2; V[2] = ONE2; V[3] = ONE2;
    ull U2[4];                      // U2[r] = (u[4a+(b^r)], same)

#pragma unroll 1
    for (int it = 0; it < 10; it++) {
        // ===== Row step: d = M0 v ; u = 1/d =====
        float D0, D1, D2, D3;
        {
            ull acc;
            MUL2(acc, M[0][0], V[0]); FMA2(acc, M[0][1], V[1], acc);
            FMA2(acc, M[0][2], V[2], acc); FMA2(acc, M[0][3], V[3], acc);
            float x, y; UNPACK2(x, y, acc); D0 = x + y;
            MUL2(acc, M[1][0], V[0]); FMA2(acc, M[1][1], V[1], acc);
            FMA2(acc, M[1][2], V[2], acc); FMA2(acc, M[1][3], V[3], acc);
            UNPACK2(x, y, acc); D1 = x + y;
            MUL2(acc, M[2][0], V[0]); FMA2(acc, M[2][1], V[1], acc);
            FMA2(acc, M[2][2], V[2], acc); FMA2(acc, M[2][3], V[3], acc);
            UNPACK2(x, y, acc); D2 = x + y;
            MUL2(acc, M[3][0], V[0]); FMA2(acc, M[3][1], V[1], acc);
            FMA2(acc, M[3][2], V[2], acc); FMA2(acc, M[3][3], V[3], acc);
            UNPACK2(x, y, acc); D3 = x + y;
        }
        // xor-slot reduce over b-quad (slot r on lane b holds row 4a+(b^r))
        D0 += __shfl_xor_sync(FULL, D2, 2);
        D1 += __shfl_xor_sync(FULL, D3, 2);
        D0 += __shfl_xor_sync(FULL, D1, 1);      // full d[4a+b]
        float u; RCPA(u, D0);                    // u = 1/d
        // u allgather into row slots
        {
            float u1 = __shfl_xor_sync(FULL, u, 1);
            float u2 = __shfl_xor_sync(FULL, u, 2);
            float u3 = __shfl_xor_sync(FULL, u, 3);
            PACK2(U2[0], u,  u ); PACK2(U2[1], u1, u1);
            PACK2(U2[2], u2, u2); PACK2(U2[3], u3, u3);
        }

        // ===== Col step: c = M0^T u ; v = 1/c  (dual accumulators) =====
        ull C0, C1, C2, C3, B0, B1, B2, B3;
        MUL2(C0, M[0][0], U2[0]); FMA2(C0, M[1][0], U2[1], C0);
        MUL2(B0, M[2][0], U2[2]); FMA2(B0, M[3][0], U2[3], B0);
        MUL2(C1, M[0][1], U2[0]); FMA2(C1, M[1][1], U2[1], C1);
        MUL2(B1, M[2][1], U2[2]); FMA2(B1, M[3][1], U2[3], B1);
        MUL2(C2, M[0][2], U2[0]); FMA2(C2, M[1][2], U2[1], C2);
        MUL2(B2, M[2][2], U2[2]); FMA2(B2, M[3][2], U2[3], B2);
        MUL2(C3, M[0][3], U2[0]); FMA2(C3, M[1][3], U2[1], C3);
        MUL2(B3, M[2][3], U2[2]); FMA2(B3, M[3][3], U2[3], B3);
        ADD2(C0, C0, B0); ADD2(C1, C1, B1);
        ADD2(C2, C2, B2); ADD2(C3, C3, B3);
        // xor-slot reduce over the 8 a-lanes
        {
            ull t;
            t = shfl_xor64(C2, 16); ADD2(C0, C0, t);
            t = shfl_xor64(C3, 16); ADD2(C1, C1, t);
            t = shfl_xor64(C1, 8);  ADD2(C0, C0, t);
        }
        // final mask-4 stage as a single scalar exchange:
        float cx, cy; UNPACK2(cx, cy, C0);
        const float send = al ? cx : cy;         // element partner needs
        const float recv = __shfl_xor_sync(FULL, send, 4);
        const float mine = al ? cy : cx;
        const float cs   = mine + recv;          // c[8b+2g+al] = c[8b+a]
        float v; RCPA(v, cs);                    // v = 1/c

        if (it == 9) {                           // final iteration: u,v -> smem
            su[4 * a + b] = u;                   // u[row 4a+b]
            sv[8 * b + a] = v;                   // v[col 8b+a]
            break;                               // no v-allgather needed
        }
        // v allgather into col-pair slots
        {
            float t4 = __shfl_xor_sync(FULL, v, 4);    // pair partner
            const float lo = al ? t4 : v;
            const float hi = al ? v  : t4;
            PACK2(V[0], lo, hi);                       // own pair g
            V[1] = shfl_xor64(V[0], 8);
            V[2] = shfl_xor64(V[0], 16);
            V[3] = shfl_xor64(V[0], 24);
        }
    }
    __syncwarp();

    // ---- Epilogue: out[i][j] = u_i * exp(M0)[i][j] * v_j ----
    // Tile still holds flat exp(M0); u,v read from smem (broadcast LDS).
    const int ch = lane & 7;                    // fixed chunk (cols 4ch..4ch+3)
    const ulonglong2 vq =
        *reinterpret_cast<const ulonglong2*>(sv + 4 * ch);   // v pairs, 1 LDS.128
#pragma unroll
    for (int k = 0; k < 8; k++) {
        const int f   = k * 32 + lane;
        const int row = f >> 3;                 // 4k + (lane>>3)
        const float uu = su[row];               // broadcast LDS (4 addrs)
        ull ud; PACK2(ud, uu, uu);
        const ulonglong2 mq =
            *reinterpret_cast<const ulonglong2*>(s + row * SROW + ch * 4);
        ull o0, o1;
        MUL2(o0, mq.x, vq.x); MUL2(o0, o0, ud);
        MUL2(o1, mq.y, vq.y); MUL2(o1, o1, ud);
        float4 t;
        UNPACK2(t.x, t.y, o0);
        UNPACK2(t.z, t.w, o1);
        dst[f] = t;
    }
}

extern "C" void kernel_launch(void* const* d_in, const int* in_sizes, int n_in,
                              void* d_out, int out_size) {
    const float* H   = (const float*)d_in[0];
    float*       out = (float*)d_out;
    const int nmat   = in_sizes[0] / 1024;          // 32*32 per matrix
    const int blocks = (nmat + WPB - 1) / WPB;
    sinkhorn_kernel<<<blocks, WPB * 32>>>(H, out, nmat);
}

// round 13
// speedup vs baseline: 1.9345x; 1.0359x over previous
#include <cuda_runtime.h>
#include <cstdint>

// ---------------------------------------------------------------------------
// Sinkhorn-Knopp, 65536 independent 32x32 fp32 matrices, 10 iterations.
//
// diag-scaling: iterate only u, v; updates simplified (eps negligible since
// sums are Theta(1)):  u = 1/d ,  v = 1/c  -- single RCP each.
//
// One warp per matrix, 8x4 lane grid: a = lane>>2 (rows 4a..4a+3),
// b = lane&3 (cols 8b..8b+7), g = a>>1. xor-slot REGISTER layout:
//   row slot r      <-> actual row       4a + (b^r)
//   col pair slot k <-> actual col pair  g^k of group b (cols 8b+2(g^k),+1)
// All cross-lane comm is SEL-free shfl_xor (20 SASS SHFL/iter ~ info floor).
// v is carried as an f32x2 pair replicated across duo lanes (mask-4 pairs),
// making the col-reduce tail and V[0] formation routing-free.
//
// Global I/O perfectly flat. Input bridges flat->slot through a per-warp
// padded smem tile (stride 36, conflict-free 128-bit ops). Epilogue reads
// the still-flat exp(M0) tile + tiny u,v boards from smem (u fetched as 2
// broadcast LDS.128 per lane via a row remap), never re-bridging the tile.
// ---------------------------------------------------------------------------

#define FMA2(d, a, b, c) \
    asm("fma.rn.f32x2 %0, %1, %2, %3;" : "=l"(d) : "l"(a), "l"(b), "l"(c))
#define MUL2(d, a, b) \
    asm("mul.rn.f32x2 %0, %1, %2;" : "=l"(d) : "l"(a), "l"(b))
#define ADD2(d, a, b) \
    asm("add.rn.f32x2 %0, %1, %2;" : "=l"(d) : "l"(a), "l"(b))
#define PACK2(d, lo, hi) \
    asm("mov.b64 %0, {%1, %2};" : "=l"(d) : "f"(lo), "f"(hi))
#define UNPACK2(lo, hi, s) \
    asm("mov.b64 {%0, %1}, %2;" : "=f"(lo), "=f"(hi) : "l"(s))
#define RCPA(d, s) \
    asm("rcp.approx.f32 %0, %1;" : "=f"(d) : "f"(s))
#define EX2A(d, s) \
    asm("ex2.approx.f32 %0, %1;" : "=f"(d) : "f"(s))

using ull = unsigned long long;

static constexpr float    EPS   = 1e-8f;
static constexpr float    SCALE = 14.4269504088896340736f;  // 10 * log2(e)
static constexpr int      WPB   = 4;                        // warps per block
static constexpr int      SROW  = 36;                       // smem row stride
static constexpr unsigned FULL  = 0xFFFFFFFFu;

__device__ __forceinline__ ull shfl_xor64(ull x, int mask) {
    return __shfl_xor_sync(FULL, x, mask);   // 2 SASS SHFLs
}

__global__ __launch_bounds__(WPB * 32, 8)
void sinkhorn_kernel(const float* __restrict__ H,
                     float* __restrict__ Out,
                     int nmat) {
    // per-warp: 32x32 padded tile + u[32] + v[32]
    __shared__ __align__(16) float S[WPB][32 * SROW + 64];

    const int lane = threadIdx.x & 31;
    const int wid  = threadIdx.x >> 5;
    const int a    = lane >> 2;      // 0..7 (rows 4a..4a+3)
    const int b    = lane & 3;       // 0..3 (cols 8b..8b+7)
    const int g    = a >> 1;         // 0..3 (own col-pair index in group)
    const int al   = a & 1;          // element within own col pair
    const int g0   = g & 1;          // pair-swap bit
    const int g1   = g >> 1;         // chunk-select bit

    const int m = blockIdx.x * WPB + wid;
    if (m >= nmat) return;           // warp-uniform

    float* s  = S[wid];
    float* su = S[wid] + 32 * SROW;        // u[32]
    float* sv = S[wid] + 32 * SROW + 32;   // v[32]
    const float4* src = reinterpret_cast<const float4*>(H)  + (size_t)m * 256;
    float4*       dst = reinterpret_cast<float4*>(Out)      + (size_t)m * 256;

    ull SC2;  PACK2(SC2, SCALE, SCALE);
    ull ONE2; PACK2(ONE2, 1.0f, 1.0f);

    // ---- Flat load (4 lines/inst), scale+exp+clamp, flat STS.128 ----
#pragma unroll
    for (int k = 0; k < 8; k++) {
        const int f = k * 32 + lane;            // float4 index in matrix
        float4 q = src[f];
        ull p0, p1;
        PACK2(p0, q.x, q.y);
        PACK2(p1, q.z, q.w);
        MUL2(p0, p0, SC2);
        MUL2(p1, p1, SC2);
        float x0, y0, x1, y1;
        UNPACK2(x0, y0, p0); UNPACK2(x1, y1, p1);
        EX2A(x0, x0); EX2A(y0, y0); EX2A(x1, x1); EX2A(y1, y1);
        q.x = fmaxf(x0, EPS); q.y = fmaxf(y0, EPS);
        q.z = fmaxf(x1, EPS); q.w = fmaxf(y1, EPS);
        const int row = f >> 3;                 // 8 float4 per row
        const int ch  = f & 7;
        *reinterpret_cast<float4*>(s + row * SROW + ch * 4) = q;
    }
    __syncwarp();

    // ---- Gather xor-slot registers via conflict-free LDS.128 ----
    // chunk Q = 2b + (g1^T) holds col pairs 2Q (lo) and 2Q+1 (hi);
    // slot 2T is the one whose pair-bit0 == g0.
    ull M[4][4];
#pragma unroll
    for (int r = 0; r < 4; r++) {
        const int R = 4 * a + (b ^ r);
#pragma unroll
        for (int T = 0; T < 2; T++) {
            const int Q = 2 * b + (g1 ^ T);
            const ulonglong2 q =
                *reinterpret_cast<const ulonglong2*>(s + R * SROW + 4 * Q);
            M[r][2 * T]     = g0 ? q.y : q.x;
            M[r][2 * T + 1] = g0 ? q.x : q.y;
        }
    }

    ull V[4];                       // V[k] = v-pair for pair g^k of group b
    V[0] = ONE2; V[1] = ONE2; V[2] = ONE2; V[3] = ONE2;
    ull U2[4];                      // U2[r] = (u[4a+(b^r)], same)

#pragma unroll 1
    for (int it = 0; it < 10; it++) {
        // ===== Row step: d = M0 v ; u = 1/d =====
        float D0, D1, D2, D3;
        {
            ull acc;
            MUL2(acc, M[0][0], V[0]); FMA2(acc, M[0][1], V[1], acc);
            FMA2(acc, M[0][2], V[2], acc); FMA2(acc, M[0][3], V[3], acc);
            float x, y; UNPACK2(x, y, acc); D0 = x + y;
            MUL2(acc, M[1][0], V[0]); FMA2(acc, M[1][1], V[1], acc);
            FMA2(acc, M[1][2], V[2], acc); FMA2(acc, M[1][3], V[3], acc);
            UNPACK2(x, y, acc); D1 = x + y;
            MUL2(acc, M[2][0], V[0]); FMA2(acc, M[2][1], V[1], acc);
            FMA2(acc, M[2][2], V[2], acc); FMA2(acc, M[2][3], V[3], acc);
            UNPACK2(x, y, acc); D2 = x + y;
            MUL2(acc, M[3][0], V[0]); FMA2(acc, M[3][1], V[1], acc);
            FMA2(acc, M[3][2], V[2], acc); FMA2(acc, M[3][3], V[3], acc);
            UNPACK2(x, y, acc); D3 = x + y;
        }
        // xor-slot reduce over b-quad (slot r on lane b holds row 4a+(b^r))
        D0 += __shfl_xor_sync(FULL, D2, 2);
        D1 += __shfl_xor_sync(FULL, D3, 2);
        D0 += __shfl_xor_sync(FULL, D1, 1);      // full d[4a+b]
        float u; RCPA(u, D0);                    // u = 1/d
        // u allgather into row slots
        {
            float u1 = __shfl_xor_sync(FULL, u, 1);
            float u2 = __shfl_xor_sync(FULL, u, 2);
            float u3 = __shfl_xor_sync(FULL, u, 3);
            PACK2(U2[0], u,  u ); PACK2(U2[1], u1, u1);
            PACK2(U2[2], u2, u2); PACK2(U2[3], u3, u3);
        }

        // ===== Col step: c = M0^T u ; v = 1/c  (dual accumulators) =====
        ull C0, C1, C2, C3, B0, B1, B2, B3;
        MUL2(C0, M[0][0], U2[0]); FMA2(C0, M[1][0], U2[1], C0);
        MUL2(B0, M[2][0], U2[2]); FMA2(B0, M[3][0], U2[3], B0);
        MUL2(C1, M[0][1], U2[0]); FMA2(C1, M[1][1], U2[1], C1);
        MUL2(B1, M[2][1], U2[2]); FMA2(B1, M[3][1], U2[3], B1);
        MUL2(C2, M[0][2], U2[0]); FMA2(C2, M[1][2], U2[1], C2);
        MUL2(B2, M[2][2], U2[2]); FMA2(B2, M[3][2], U2[3], B2);
        MUL2(C3, M[0][3], U2[0]); FMA2(C3, M[1][3], U2[1], C3);
        MUL2(B3, M[2][3], U2[2]); FMA2(B3, M[3][3], U2[3], B3);
        ADD2(C0, C0, B0); ADD2(C1, C1, B1);
        ADD2(C2, C2, B2); ADD2(C3, C3, B3);
        // xor-slot reduce over the 8 a-lanes (pair payloads, duo-complete)
        {
            ull t;
            t = shfl_xor64(C2, 16); ADD2(C0, C0, t);
            t = shfl_xor64(C3, 16); ADD2(C1, C1, t);
            t = shfl_xor64(C1, 8);  ADD2(C0, C0, t);
            t = shfl_xor64(C0, 4);  ADD2(C0, C0, t);  // full pair on duo
        }
        // v-pair update (replicated across duo; no routing selects)
        float vx, vy;
        {
            float cx, cy; UNPACK2(cx, cy, C0);
            RCPA(vx, cx); RCPA(vy, cy);
        }

        if (it == 9) {                           // final iter: u,v -> smem
            su[4 * a + b] = u;                   // u[row 4a+b]
            if (al == 0) {                       // one duo lane stores v pair
                sv[8 * b + 2 * g]     = vx;
                sv[8 * b + 2 * g + 1] = vy;
            }
            break;                               // no v-allgather needed
        }
        // v allgather into col-pair slots
        PACK2(V[0], vx, vy);                     // own pair g
        V[1] = shfl_xor64(V[0], 8);
        V[2] = shfl_xor64(V[0], 16);
        V[3] = shfl_xor64(V[0], 24);
    }
    __syncwarp();

    // ---- Epilogue: out[i][j] = u_i * exp(M0)[i][j] * v_j ----
    // Tile still holds flat exp(M0). Row remap: lane covers rows
    // ro*8 .. ro*8+7 (ro = lane>>3) so its 8 u's are contiguous in smem
    // (2 broadcast LDS.128). Global stores remain 4x128B lines per inst.
    const int ch = lane & 7;                    // fixed chunk (cols 4ch..4ch+3)
    const int ro = lane >> 3;                   // octet -> row group
    const ulonglong2 vq =
        *reinterpret_cast<const ulonglong2*>(sv + 4 * ch);   // v pairs
    const float4 ua = *reinterpret_cast<const float4*>(su + ro * 8);
    const float4 ub = *reinterpret_cast<const float4*>(su + ro * 8 + 4);
    const float us[8] = { ua.x, ua.y, ua.z, ua.w, ub.x, ub.y, ub.z, ub.w };
#pragma unroll
    for (int k = 0; k < 8; k++) {
        const int row = ro * 8 + k;
        ull ud; PACK2(ud, us[k], us[k]);
        const ulonglong2 mq =
            *reinterpret_cast<const ulonglong2*>(s + row * SROW + ch * 4);
        ull o0, o1;
        MUL2(o0, mq.x, vq.x); MUL2(o0, o0, ud);
        MUL2(o1, mq.y, vq.y); MUL2(o1, o1, ud);
        float4 t;
        UNPACK2(t.x, t.y, o0);
        UNPACK2(t.z, t.w, o1);
        dst[row * 8 + ch] = t;
    }
}

extern "C" void kernel_launch(void* const* d_in, const int* in_sizes, int n_in,
                              void* d_out, int out_size) {
    const float* H   = (const float*)d_in[0];
    float*       out = (float*)d_out;
    const int nmat   = in_sizes[0] / 1024;          // 32*32 per matrix
    const int blocks = (nmat + WPB - 1) / WPB;
    sinkhorn_kernel<<<blocks, WPB * 32>>>(H, out, nmat);
}